// round 1
// baseline (speedup 1.0000x reference)
#include <cuda_runtime.h>
#include <math.h>

#define N_NODES 512
#define DSTATE  32
#define MDIM    32
#define HMSG    64
#define NSTEPS  5
#define TI      16   // i-rows per block (reduced intra-warp)
#define TJ      8    // j-cols per block

// Persistent scratch (device globals: no allocation allowed)
__device__ float g_h[N_NODES * DSTATE];
__device__ float g_u[N_NODES * HMSG];
__device__ float g_v[N_NODES * HMSG];
__device__ float g_msgsum[N_NODES * MDIM];

// ---------------------------------------------------------------------------
// Zero the state at the start of every launch (deterministic replay).
__global__ void init_kernel() {
    int idx = blockIdx.x * blockDim.x + threadIdx.x;
    if (idx < N_NODES * DSTATE) g_h[idx] = 0.0f;
}

// ---------------------------------------------------------------------------
// Per-node prep: u[i] = h[i]@Wi.T + b[i]*wbi ; v[j] = h[j]@Wj.T + b[j]*wbj + b1
// Also zeroes msg_sum for the upcoming pairs kernel.
// mp_W1 is (64, 67): [:, :32]=Wi, [:,32:64]=Wj, [:,64]=wJ, [:,65]=wbi, [:,66]=wbj
__global__ void prep_kernel(const float* __restrict__ b,
                            const float* __restrict__ W1,
                            const float* __restrict__ b1) {
    int i = blockIdx.x;
    int t = threadIdx.x;  // 64 threads
    __shared__ float hs[DSTATE];
    if (t < DSTATE) {
        hs[t] = g_h[i * DSTATE + t];
        g_msgsum[i * MDIM + t] = 0.0f;
    }
    __syncthreads();
    const float* w = W1 + t * 67;
    float bi = b[i];
    float au = bi * w[65];
    float av = bi * w[66] + b1[t];
#pragma unroll
    for (int d2 = 0; d2 < DSTATE; d2++) {
        float hv = hs[d2];
        au = fmaf(hv, w[d2], au);
        av = fmaf(hv, w[DSTATE + d2], av);
    }
    g_u[i * HMSG + t] = au;
    g_v[i * HMSG + t] = av;
}

// ---------------------------------------------------------------------------
// Heavy kernel: one thread = one (i,j) pair.
//   m1_l = relu(u[i][l] + v[j][l] + J[i][j]*wJ[l])     (never materialized)
//   acc[k] = b2[k] + sum_l m1_l * W2[k][l]             (W2 transposed in smem)
//   msg[o] = relu(b3[o] + sum_k relu(acc[k]) * W3[o][k])
//   reduce msg over the 16 i's in each 16-lane group, atomicAdd into msg_sum[j].
__global__ __launch_bounds__(128, 4) void pairs_kernel(
    const float* __restrict__ J,  const float* __restrict__ W1,
    const float* __restrict__ W2, const float* __restrict__ b2,
    const float* __restrict__ W3, const float* __restrict__ b3) {
    __shared__ float sW2T[HMSG * HMSG];   // [l][k] : k contiguous -> float4
    __shared__ float sW3T[HMSG * MDIM];   // [k][o] : o contiguous -> float4
    __shared__ float sU[TI * 65];         // stride 65: conflict-free across i-lanes
    __shared__ float sV[TJ * HMSG];       // broadcast within 16-lane groups
    __shared__ float sWJ[HMSG];
    __shared__ float sB2[HMSG];
    __shared__ float sB3[MDIM];

    int tid = threadIdx.x;
    int i0 = blockIdx.x * TI;
    int j0 = blockIdx.y * TJ;

    // Stage weights (coalesced gmem reads, scatter into smem once per block)
    for (int x = tid; x < HMSG * HMSG; x += 128) {
        int k = x >> 6, l = x & 63;
        sW2T[l * HMSG + k] = W2[x];
    }
    for (int x = tid; x < MDIM * HMSG; x += 128) {
        int o = x >> 6, k = x & 63;
        sW3T[k * MDIM + o] = W3[x];
    }
    for (int x = tid; x < TI * HMSG; x += 128) {
        int ii = x >> 6, l = x & 63;
        sU[ii * 65 + l] = g_u[(i0 + ii) * HMSG + l];
    }
    for (int x = tid; x < TJ * HMSG; x += 128) {
        int jj = x >> 6, l = x & 63;
        sV[jj * HMSG + l] = g_v[(j0 + jj) * HMSG + l];
    }
    if (tid < HMSG) {
        sWJ[tid] = W1[tid * 67 + 64];
        sB2[tid] = b2[tid];
    } else if (tid < HMSG + MDIM) {
        sB3[tid - HMSG] = b3[tid - HMSG];
    }
    __syncthreads();

    int il = tid & (TI - 1);
    int jl = tid >> 4;
    float Jij = J[(i0 + il) * N_NODES + (j0 + jl)];
    const float* uR = &sU[il * 65];
    const float* vR = &sV[jl * HMSG];

    float acc[HMSG];
#pragma unroll
    for (int k = 0; k < HMSG; k++) acc[k] = sB2[k];

    // Layer 1 fused into layer-2 accumulation: relu(pre_l) consumed on the fly.
#pragma unroll 4
    for (int l = 0; l < HMSG; l++) {
        float ml = fmaf(Jij, sWJ[l], uR[l] + vR[l]);
        ml = fmaxf(ml, 0.0f);
        const float4* wrow = (const float4*)&sW2T[l * HMSG];
#pragma unroll
        for (int k4 = 0; k4 < HMSG / 4; k4++) {
            float4 wv = wrow[k4];
            acc[k4 * 4 + 0] = fmaf(ml, wv.x, acc[k4 * 4 + 0]);
            acc[k4 * 4 + 1] = fmaf(ml, wv.y, acc[k4 * 4 + 1]);
            acc[k4 * 4 + 2] = fmaf(ml, wv.z, acc[k4 * 4 + 2]);
            acc[k4 * 4 + 3] = fmaf(ml, wv.w, acc[k4 * 4 + 3]);
        }
    }

    float msg[MDIM];
#pragma unroll
    for (int o = 0; o < MDIM; o++) msg[o] = sB3[o];

#pragma unroll
    for (int k = 0; k < HMSG; k++) {
        float mk = fmaxf(acc[k], 0.0f);
        const float4* wrow = (const float4*)&sW3T[k * MDIM];
#pragma unroll
        for (int o4 = 0; o4 < MDIM / 4; o4++) {
            float4 wv = wrow[o4];
            msg[o4 * 4 + 0] = fmaf(mk, wv.x, msg[o4 * 4 + 0]);
            msg[o4 * 4 + 1] = fmaf(mk, wv.y, msg[o4 * 4 + 1]);
            msg[o4 * 4 + 2] = fmaf(mk, wv.z, msg[o4 * 4 + 2]);
            msg[o4 * 4 + 3] = fmaf(mk, wv.w, msg[o4 * 4 + 3]);
        }
    }

#pragma unroll
    for (int o = 0; o < MDIM; o++) msg[o] = fmaxf(msg[o], 0.0f);

    // Reduce over the 16 i-lanes within each 16-lane segment.
#pragma unroll
    for (int off = 8; off >= 1; off >>= 1) {
#pragma unroll
        for (int o = 0; o < MDIM; o++)
            msg[o] += __shfl_down_sync(0xffffffffu, msg[o], off, 16);
    }
    if (il == 0) {
        float* dst = &g_msgsum[(j0 + jl) * MDIM];
#pragma unroll
        for (int o = 0; o < MDIM; o++) atomicAdd(&dst[o], msg[o]);
    }
}

// ---------------------------------------------------------------------------
// GRU update: one block per node, thread t = state dim t.
__global__ void gru_kernel(const float* __restrict__ Wih,
                           const float* __restrict__ Whh,
                           const float* __restrict__ bih,
                           const float* __restrict__ bhh) {
    int i = blockIdx.x;
    int t = threadIdx.x;  // 32 threads
    __shared__ float xs[2 * DSTATE];  // [h, msg_sum]
    xs[t] = g_h[i * DSTATE + t];
    xs[DSTATE + t] = g_msgsum[i * MDIM + t];
    __syncthreads();

    float gr = bih[t], gz = bih[DSTATE + t], gn = bih[2 * DSTATE + t];
    const float* wr = Wih + t * 64;
    const float* wz = Wih + (DSTATE + t) * 64;
    const float* wn = Wih + (2 * DSTATE + t) * 64;
#pragma unroll
    for (int c = 0; c < 64; c++) {
        float xv = xs[c];
        gr = fmaf(wr[c], xv, gr);
        gz = fmaf(wz[c], xv, gz);
        gn = fmaf(wn[c], xv, gn);
    }
    float hr = bhh[t], hz = bhh[DSTATE + t], hn = bhh[2 * DSTATE + t];
    const float* vr = Whh + t * DSTATE;
    const float* vz = Whh + (DSTATE + t) * DSTATE;
    const float* vn = Whh + (2 * DSTATE + t) * DSTATE;
#pragma unroll
    for (int c = 0; c < DSTATE; c++) {
        float hv = xs[c];
        hr = fmaf(vr[c], hv, hr);
        hz = fmaf(vz[c], hv, hz);
        hn = fmaf(vn[c], hv, hn);
    }
    float r = 1.0f / (1.0f + expf(-(gr + hr)));
    float z = 1.0f / (1.0f + expf(-(gz + hz)));
    float ng = tanhf(gn + r * hn);
    g_h[i * DSTATE + t] = (1.0f - z) * ng + z * xs[t];
}

// ---------------------------------------------------------------------------
// Readout: relu MLP 32 -> 64 -> 64 -> 2, sigmoid.
__global__ void readout_kernel(const float* __restrict__ rW1, const float* __restrict__ rb1,
                               const float* __restrict__ rW2, const float* __restrict__ rb2,
                               const float* __restrict__ rW3, const float* __restrict__ rb3,
                               float* __restrict__ out) {
    int i = blockIdx.x;
    int t = threadIdx.x;  // 64 threads
    __shared__ float hs[DSTATE];
    __shared__ float y1[64];
    __shared__ float y2[64];
    if (t < DSTATE) hs[t] = g_h[i * DSTATE + t];
    __syncthreads();

    float a = rb1[t];
#pragma unroll
    for (int d2 = 0; d2 < DSTATE; d2++) a = fmaf(rW1[t * DSTATE + d2], hs[d2], a);
    y1[t] = fmaxf(a, 0.0f);
    __syncthreads();

    float c = rb2[t];
#pragma unroll
    for (int k = 0; k < 64; k++) c = fmaf(rW2[t * 64 + k], y1[k], c);
    y2[t] = fmaxf(c, 0.0f);
    __syncthreads();

    if (t < 2) {
        float e = rb3[t];
#pragma unroll
        for (int k = 0; k < 64; k++) e = fmaf(rW3[t * 64 + k], y2[k], e);
        e = fmaxf(e, 0.0f);
        out[i * 2 + t] = 1.0f / (1.0f + expf(-e));
    }
}

// ---------------------------------------------------------------------------
extern "C" void kernel_launch(void* const* d_in, const int* in_sizes, int n_in,
                              void* d_out, int out_size) {
    const float* J   = (const float*)d_in[0];
    const float* b   = (const float*)d_in[1];
    const float* W1  = (const float*)d_in[2];
    const float* b1  = (const float*)d_in[3];
    const float* W2  = (const float*)d_in[4];
    const float* b2  = (const float*)d_in[5];
    const float* W3  = (const float*)d_in[6];
    const float* b3  = (const float*)d_in[7];
    const float* Wih = (const float*)d_in[8];
    const float* Whh = (const float*)d_in[9];
    const float* bih = (const float*)d_in[10];
    const float* bhh = (const float*)d_in[11];
    const float* rW1 = (const float*)d_in[12];
    const float* rb1 = (const float*)d_in[13];
    const float* rW2 = (const float*)d_in[14];
    const float* rb2 = (const float*)d_in[15];
    const float* rW3 = (const float*)d_in[16];
    const float* rb3 = (const float*)d_in[17];
    float* out = (float*)d_out;

    init_kernel<<<(N_NODES * DSTATE + 255) / 256, 256>>>();
    for (int s = 0; s < NSTEPS; s++) {
        prep_kernel<<<N_NODES, HMSG>>>(b, W1, b1);
        dim3 grid(N_NODES / TI, N_NODES / TJ);
        pairs_kernel<<<grid, 128>>>(J, W1, W2, b2, W3, b3);
        gru_kernel<<<N_NODES, DSTATE>>>(Wih, Whh, bih, bhh);
    }
    readout_kernel<<<N_NODES, 64>>>(rW1, rb1, rW2, rb2, rW3, rb3, out);
}

// round 4
// speedup vs baseline: 4.4631x; 4.4631x over previous
#include <cuda_runtime.h>
#include <cuda_bf16.h>
#include <cstdint>
#include <math.h>

#define N_NODES 512
#define DSTATE  32
#define MDIM    32
#define HMSG    64
#define NSTEPS  5
#define TIp     16   // i rows per tile
#define TJp     8    // j cols per tile
#define ASTR    144  // padded row stride in bytes (72 bf16) -> conflict-free

// Persistent scratch (device globals: no allocation allowed)
__device__ float g_h[N_NODES * DSTATE];
__device__ float g_u[N_NODES * HMSG];
__device__ float g_v[N_NODES * HMSG];
__device__ float g_msgsum[N_NODES * MDIM];

__device__ __forceinline__ uint32_t bf2_u32(float lo, float hi) {
    __nv_bfloat162 bb = __floats2bfloat162_rn(lo, hi);
    return *reinterpret_cast<uint32_t*>(&bb);
}

// m16n8k16 bf16 mma, fp32 accumulate (baseline PTX, sm_80+; HMMA on Blackwell)
__device__ __forceinline__ void mma16816(float* c, const uint32_t* a,
                                         uint32_t b0, uint32_t b1) {
    asm volatile(
        "mma.sync.aligned.m16n8k16.row.col.f32.bf16.bf16.f32 "
        "{%0,%1,%2,%3}, {%4,%5,%6,%7}, {%8,%9}, {%0,%1,%2,%3};"
        : "+f"(c[0]), "+f"(c[1]), "+f"(c[2]), "+f"(c[3])
        : "r"(a[0]), "r"(a[1]), "r"(a[2]), "r"(a[3]), "r"(b0), "r"(b1));
}

#define LDB32(base, r, c) (*(const uint32_t*)((base) + (r) * ASTR + (c) * 2))

// ============================ kernels =====================================
__global__ void init_kernel() {
    int idx = blockIdx.x * blockDim.x + threadIdx.x;
    if (idx < N_NODES * DSTATE) g_h[idx] = 0.0f;
}

// prep: 8 nodes x 64 threads per block. Also zeroes msg_sum.
__global__ __launch_bounds__(512) void prep_kernel(const float* __restrict__ b,
                                                   const float* __restrict__ W1,
                                                   const float* __restrict__ b1) {
    __shared__ float sW1[64 * 69];
    __shared__ float sh[8 * 32];
    int tid = threadIdx.x;
    for (int x = tid; x < 64 * 67; x += 512) {
        int r = x / 67, c = x % 67;
        sW1[r * 69 + c] = W1[x];
    }
    int nl = tid >> 6, t = tid & 63;
    int node = blockIdx.x * 8 + nl;
    if (t < 32) sh[nl * 32 + t] = g_h[node * 32 + t];
    else g_msgsum[node * 32 + (t - 32)] = 0.0f;
    __syncthreads();
    const float* w = &sW1[t * 69];
    float bi = b[node];
    float au = bi * w[65];
    float av = bi * w[66] + b1[t];
    const float* hr = &sh[nl * 32];
#pragma unroll
    for (int c = 0; c < 32; c++) {
        float hv = hr[c];
        au = fmaf(hv, w[c], au);
        av = fmaf(hv, w[32 + c], av);
    }
    g_u[node * 64 + t] = au;
    g_v[node * 64 + t] = av;
}

// pairs: one block = 16i x 8j = 128 pairs (M=128); two bf16 HMMA GEMMs.
__global__ __launch_bounds__(128) void pairs_kernel(
    const float* __restrict__ J,  const float* __restrict__ W1,
    const float* __restrict__ W2, const float* __restrict__ b2,
    const float* __restrict__ W3, const float* __restrict__ b3) {
    __shared__ __align__(16) uint8_t sA[128 * ASTR];   // bf16 [128][72]: A1 then A2
    __shared__ __align__(16) uint8_t sW2[64 * ASTR];   // bf16 W2 [64][72] (N-major, K contig)
    __shared__ __align__(16) uint8_t sW3[32 * ASTR];   // bf16 W3 [32][72]
    __shared__ float sU[TIp * 65];
    __shared__ float sV[TJp * 65];
    __shared__ float sWJ[64], sB2[64], sB3[32];

    int tid = threadIdx.x;
    int w = tid >> 5, l = tid & 31;
    int lr = l >> 2, lc = l & 3;
    int i0 = blockIdx.x * TIp, j0 = blockIdx.y * TJp;

    // ---- stage weights (f32 -> bf16, padded rows) ----
    for (int x = tid; x < 512; x += 128) {        // W2: 64 rows x 8 chunks
        int k = x >> 3, c8 = x & 7;
        const float4* src = (const float4*)(W2 + k * 64 + c8 * 8);
        float4 f0 = src[0], f1 = src[1];
        *(uint4*)(sW2 + k * ASTR + c8 * 16) =
            make_uint4(bf2_u32(f0.x, f0.y), bf2_u32(f0.z, f0.w),
                       bf2_u32(f1.x, f1.y), bf2_u32(f1.z, f1.w));
    }
    for (int x = tid; x < 256; x += 128) {        // W3: 32 rows x 8 chunks
        int k = x >> 3, c8 = x & 7;
        const float4* src = (const float4*)(W3 + k * 64 + c8 * 8);
        float4 f0 = src[0], f1 = src[1];
        *(uint4*)(sW3 + k * ASTR + c8 * 16) =
            make_uint4(bf2_u32(f0.x, f0.y), bf2_u32(f0.z, f0.w),
                       bf2_u32(f1.x, f1.y), bf2_u32(f1.z, f1.w));
    }
    for (int x = tid; x < TIp * 64; x += 128) {
        int r = x >> 6, c = x & 63;
        sU[r * 65 + c] = g_u[(i0 + r) * 64 + c];
    }
    for (int x = tid; x < TJp * 64; x += 128) {
        int r = x >> 6, c = x & 63;
        sV[r * 65 + c] = g_v[(j0 + r) * 64 + c];
    }
    if (tid < 64) {
        sWJ[tid] = W1[tid * 67 + 64];
        sB2[tid] = b2[tid];
    } else if (tid < 96) {
        sB3[tid - 64] = b3[tid - 64];
    }
    __syncthreads();

    // ---- build A1 row (this thread's pair): relu(u+v+J*wJ) -> bf16 ----
    {
        int il = tid & 15, jl = tid >> 4;
        float Jij = J[(i0 + il) * N_NODES + (j0 + jl)];
        const float* u = &sU[il * 65];
        const float* v = &sV[jl * 65];
        uint8_t* row = sA + tid * ASTR;
#pragma unroll
        for (int g = 0; g < 8; g++) {
            uint32_t wv[4];
#pragma unroll
            for (int e = 0; e < 4; e++) {
                int c = g * 8 + e * 2;
                float p0 = fmaxf(fmaf(Jij, sWJ[c], u[c] + v[c]), 0.0f);
                float p1 = fmaxf(fmaf(Jij, sWJ[c + 1], u[c + 1] + v[c + 1]), 0.0f);
                wv[e] = bf2_u32(p0, p1);
            }
            *(uint4*)(row + g * 16) = make_uint4(wv[0], wv[1], wv[2], wv[3]);
        }
    }
    __syncwarp();

    // ---- GEMM1: D1[128x64] = A1 @ W2^T ; warp w owns M rows [32w,32w+32) ----
    float acc[2][8][4];
#pragma unroll
    for (int mt = 0; mt < 2; mt++)
#pragma unroll
        for (int nt = 0; nt < 8; nt++)
#pragma unroll
            for (int e = 0; e < 4; e++) acc[mt][nt][e] = 0.0f;

#pragma unroll
    for (int ks = 0; ks < 4; ks++) {
        int k0 = ks * 16;
        uint32_t a[2][4];
#pragma unroll
        for (int mt = 0; mt < 2; mt++) {
            int m = w * 32 + mt * 16 + lr;
            a[mt][0] = LDB32(sA, m,     k0 + lc * 2);
            a[mt][1] = LDB32(sA, m + 8, k0 + lc * 2);
            a[mt][2] = LDB32(sA, m,     k0 + 8 + lc * 2);
            a[mt][3] = LDB32(sA, m + 8, k0 + 8 + lc * 2);
        }
#pragma unroll
        for (int nt = 0; nt < 8; nt++) {
            uint32_t b0 = LDB32(sW2, nt * 8 + lr, k0 + lc * 2);
            uint32_t b1 = LDB32(sW2, nt * 8 + lr, k0 + 8 + lc * 2);
            mma16816(acc[0][nt], a[0], b0, b1);
            mma16816(acc[1][nt], a[1], b0, b1);
        }
    }

    // ---- epilogue 1: relu(D1 + b2) -> bf16 back into sA (same warp rows) ----
#pragma unroll
    for (int mt = 0; mt < 2; mt++) {
        int m = w * 32 + mt * 16 + lr;
#pragma unroll
        for (int nt = 0; nt < 8; nt++) {
            int n = nt * 8 + lc * 2;
            float f0 = fmaxf(acc[mt][nt][0] + sB2[n],     0.0f);
            float f1 = fmaxf(acc[mt][nt][1] + sB2[n + 1], 0.0f);
            float f2 = fmaxf(acc[mt][nt][2] + sB2[n],     0.0f);
            float f3 = fmaxf(acc[mt][nt][3] + sB2[n + 1], 0.0f);
            *(uint32_t*)(sA + m * ASTR + n * 2)       = bf2_u32(f0, f1);
            *(uint32_t*)(sA + (m + 8) * ASTR + n * 2) = bf2_u32(f2, f3);
        }
    }
    __syncwarp();

    // ---- GEMM2: D2[128x32] = A2 @ W3^T ----
    float acc2[2][4][4];
#pragma unroll
    for (int mt = 0; mt < 2; mt++)
#pragma unroll
        for (int nt = 0; nt < 4; nt++)
#pragma unroll
            for (int e = 0; e < 4; e++) acc2[mt][nt][e] = 0.0f;

#pragma unroll
    for (int ks = 0; ks < 4; ks++) {
        int k0 = ks * 16;
        uint32_t a[2][4];
#pragma unroll
        for (int mt = 0; mt < 2; mt++) {
            int m = w * 32 + mt * 16 + lr;
            a[mt][0] = LDB32(sA, m,     k0 + lc * 2);
            a[mt][1] = LDB32(sA, m + 8, k0 + lc * 2);
            a[mt][2] = LDB32(sA, m,     k0 + 8 + lc * 2);
            a[mt][3] = LDB32(sA, m + 8, k0 + 8 + lc * 2);
        }
#pragma unroll
        for (int nt = 0; nt < 4; nt++) {
            uint32_t b0 = LDB32(sW3, nt * 8 + lr, k0 + lc * 2);
            uint32_t b1 = LDB32(sW3, nt * 8 + lr, k0 + 8 + lc * 2);
            mma16816(acc2[0][nt], a[0], b0, b1);
            mma16816(acc2[1][nt], a[1], b0, b1);
        }
    }

    // ---- epilogue 2: relu(D2 + b3); sum over 16 i-lanes; atomicAdd ----
    // Row m = 32w + 16*mt + {lr, lr+8}: jl = 2w + mt fixed per mt; rows span il 0..15.
#pragma unroll
    for (int mt = 0; mt < 2; mt++) {
        int jl = 2 * w + mt;
#pragma unroll
        for (int nt = 0; nt < 4; nt++) {
            int n = nt * 8 + lc * 2;
            float s0 = fmaxf(acc2[mt][nt][0] + sB3[n],     0.0f)
                     + fmaxf(acc2[mt][nt][2] + sB3[n],     0.0f);
            float s1 = fmaxf(acc2[mt][nt][1] + sB3[n + 1], 0.0f)
                     + fmaxf(acc2[mt][nt][3] + sB3[n + 1], 0.0f);
#pragma unroll
            for (int off = 4; off <= 16; off <<= 1) {
                s0 += __shfl_xor_sync(0xffffffffu, s0, off);
                s1 += __shfl_xor_sync(0xffffffffu, s1, off);
            }
            if (l < 4) {
                float* dst = &g_msgsum[(j0 + jl) * MDIM + n];
                atomicAdd(dst, s0);
                atomicAdd(dst + 1, s1);
            }
        }
    }
}

// GRU: 16 nodes per block (one node per warp), weights transposed in smem.
__global__ __launch_bounds__(512) void gru_kernel(const float* __restrict__ Wih,
                                                  const float* __restrict__ Whh,
                                                  const float* __restrict__ bih,
                                                  const float* __restrict__ bhh) {
    __shared__ float sWi[64 * 97];  // [c][g]
    __shared__ float sWh[32 * 97];
    __shared__ float sbi[96], sbh[96];
    __shared__ float sx[16 * 64];
    int tid = threadIdx.x;
    for (int x = tid; x < 96 * 64; x += 512) {
        int g = x >> 6, c = x & 63;
        sWi[c * 97 + g] = Wih[x];
    }
    for (int x = tid; x < 96 * 32; x += 512) {
        int g = x >> 5, c = x & 31;
        sWh[c * 97 + g] = Whh[x];
    }
    if (tid < 96) { sbi[tid] = bih[tid]; sbh[tid] = bhh[tid]; }
    int nl = tid >> 5, t = tid & 31;
    int node = blockIdx.x * 16 + nl;
    float hval = g_h[node * 32 + t];
    sx[nl * 64 + t] = hval;
    sx[nl * 64 + 32 + t] = g_msgsum[node * 32 + t];
    __syncthreads();
    const float* x = &sx[nl * 64];
    float gr = sbi[t], gz = sbi[32 + t], gn = sbi[64 + t];
#pragma unroll
    for (int c = 0; c < 64; c++) {
        float xv = x[c];
        const float* wp = &sWi[c * 97];
        gr = fmaf(wp[t], xv, gr);
        gz = fmaf(wp[32 + t], xv, gz);
        gn = fmaf(wp[64 + t], xv, gn);
    }
    float hr = sbh[t], hz = sbh[32 + t], hn = sbh[64 + t];
#pragma unroll
    for (int c = 0; c < 32; c++) {
        float hv = x[c];
        const float* wp = &sWh[c * 97];
        hr = fmaf(wp[t], hv, hr);
        hz = fmaf(wp[32 + t], hv, hz);
        hn = fmaf(wp[64 + t], hv, hn);
    }
    float r = 1.0f / (1.0f + expf(-(gr + hr)));
    float z = 1.0f / (1.0f + expf(-(gz + hz)));
    float ng = tanhf(gn + r * hn);
    g_h[node * 32 + t] = (1.0f - z) * ng + z * hval;
}

// readout: 8 nodes x 64 threads per block.
__global__ __launch_bounds__(512) void readout_kernel(
    const float* __restrict__ rW1, const float* __restrict__ rb1,
    const float* __restrict__ rW2, const float* __restrict__ rb2,
    const float* __restrict__ rW3, const float* __restrict__ rb3,
    float* __restrict__ out) {
    __shared__ float sw1[64 * 33];
    __shared__ float sw2[64 * 65];
    __shared__ float sw3[2 * 64];
    __shared__ float sh[8 * 32];
    __shared__ float sy1[8 * 64];
    __shared__ float sy2[8 * 64];
    int tid = threadIdx.x;
    for (int x = tid; x < 64 * 32; x += 512) {
        int r = x >> 5, c = x & 31;
        sw1[r * 33 + c] = rW1[x];
    }
    for (int x = tid; x < 64 * 64; x += 512) {
        int r = x >> 6, c = x & 63;
        sw2[r * 65 + c] = rW2[x];
    }
    if (tid < 128) sw3[tid] = rW3[tid];
    int nl = tid >> 6, t = tid & 63;
    int node = blockIdx.x * 8 + nl;
    if (t < 32) sh[nl * 32 + t] = g_h[node * 32 + t];
    __syncthreads();
    float a = rb1[t];
    const float* w1 = &sw1[t * 33];
    const float* hr = &sh[nl * 32];
#pragma unroll
    for (int c = 0; c < 32; c++) a = fmaf(w1[c], hr[c], a);
    sy1[nl * 64 + t] = fmaxf(a, 0.0f);
    __syncthreads();
    float c2 = rb2[t];
    const float* w2 = &sw2[t * 65];
    const float* y1 = &sy1[nl * 64];
#pragma unroll
    for (int k = 0; k < 64; k++) c2 = fmaf(w2[k], y1[k], c2);
    sy2[nl * 64 + t] = fmaxf(c2, 0.0f);
    __syncthreads();
    if (t < 2) {
        float e = rb3[t];
        const float* y2 = &sy2[nl * 64];
#pragma unroll
        for (int k = 0; k < 64; k++) e = fmaf(sw3[t * 64 + k], y2[k], e);
        e = fmaxf(e, 0.0f);
        out[node * 2 + t] = 1.0f / (1.0f + expf(-e));
    }
}

// ---------------------------------------------------------------------------
extern "C" void kernel_launch(void* const* d_in, const int* in_sizes, int n_in,
                              void* d_out, int out_size) {
    const float* J   = (const float*)d_in[0];
    const float* b   = (const float*)d_in[1];
    const float* W1  = (const float*)d_in[2];
    const float* b1  = (const float*)d_in[3];
    const float* W2  = (const float*)d_in[4];
    const float* b2  = (const float*)d_in[5];
    const float* W3  = (const float*)d_in[6];
    const float* b3  = (const float*)d_in[7];
    const float* Wih = (const float*)d_in[8];
    const float* Whh = (const float*)d_in[9];
    const float* bih = (const float*)d_in[10];
    const float* bhh = (const float*)d_in[11];
    const float* rW1 = (const float*)d_in[12];
    const float* rb1 = (const float*)d_in[13];
    const float* rW2 = (const float*)d_in[14];
    const float* rb2 = (const float*)d_in[15];
    const float* rW3 = (const float*)d_in[16];
    const float* rb3 = (const float*)d_in[17];
    float* out = (float*)d_out;

    init_kernel<<<(N_NODES * DSTATE + 255) / 256, 256>>>();
    for (int s = 0; s < NSTEPS; s++) {
        prep_kernel<<<N_NODES / 8, 512>>>(b, W1, b1);
        dim3 grid(N_NODES / TIp, N_NODES / TJp);
        pairs_kernel<<<grid, 128>>>(J, W1, W2, b2, W3, b3);
        gru_kernel<<<N_NODES / 16, 512>>>(Wih, Whh, bih, bhh);
    }
    readout_kernel<<<N_NODES / 8, 512>>>(rW1, rb1, rW2, rb2, rW3, rb3, out);
}